// round 3
// baseline (speedup 1.0000x reference)
#include <cuda_runtime.h>
#include <math.h>

// Problem constants (from setup_inputs; p_sample=100 fixed)
#define Bn   512
#define Kd   256
#define KH   128
#define Gg   384     // 3*KH
#define Tt   101     // p_sample+1
#define Ff   16
#define MGX  (Bn*Tt)   // 51712 = 404*128 exactly
#define GXB2 (MGX/128) // 404 gemm m-tiles
#define CPB  128       // copy blocks fused into k_gx
#define GRUCP 20       // copy CTAs fused into k_gru

// ---------------- packed fp32x2 helpers (sm_103a FFMA2) ----------------
typedef unsigned long long ull;
__device__ __forceinline__ ull ff2(ull a, ull b, ull c) {
    ull d;
    asm("fma.rn.f32x2 %0, %1, %2, %3;" : "=l"(d) : "l"(a), "l"(b), "l"(c));
    return d;
}
__device__ __forceinline__ ull dup2(float x) {
    ull r; asm("mov.b64 %0, {%1, %1};" : "=l"(r) : "f"(x)); return r;
}
__device__ __forceinline__ float2 unpk2(ull v) {
    float2 r; asm("mov.b64 {%0, %1}, %2;" : "=f"(r.x), "=f"(r.y) : "l"(v)); return r;
}

// ---------------- scratch (device globals: allocation-free) ----------------
__device__ float g_gx[MGX * Gg];          // [m=b*101+t][g]
__device__ float g_WihT[Kd * Gg];         // [k][g]
__device__ float g_WkT[Ff * KH * Kd];     // [f][h][k]
__device__ float g_ctT[KH * Bn];          // [h][b]
__device__ float g_predT[Ff * Kd * Bn];   // [f][k][c]
__device__ float g_encT[Ff * Kd * Bn];    // [f][k][b]
__device__ float g_totals[Ff * Bn * Bn];  // [f][b][c]
__device__ float g_lse15[Bn];
__device__ float g_diag[Ff * Bn];
__device__ int   g_ok[Bn];

// ---------------- weight transposes (tiny) ----------------
__global__ void k_transpose_wih(const float* __restrict__ W) {
    int idx = blockIdx.x * 256 + threadIdx.x;           // 384*256
    if (idx < Gg * Kd) {
        int g = idx / Kd, k = idx % Kd;
        g_WihT[k * Gg + g] = W[idx];
    }
}
__global__ void k_transpose_wk(const float* __restrict__ W) {
    int idx = blockIdx.x * 256 + threadIdx.x;           // 16*256*128
    if (idx < Ff * Kd * KH) {
        int f = idx >> 15, r = idx & 32767, k = r >> 7, h = r & 127;
        g_WkT[f * (KH * Kd) + h * Kd + k] = W[idx];
    }
}

// ---------------- encoded gather: encT[f][k][b] = z[b][k][101+f] -----------
__global__ void k_enc(const float* __restrict__ z) {
    int idx = blockIdx.x * 256 + threadIdx.x;    // 16*256*512
    if (idx < Ff * Kd * Bn) {
        int b = idx & 511, k = (idx >> 9) & 255, f = idx >> 17;
        g_encT[idx] = z[(size_t)b * (Kd * 256) + k * 256 + (Tt + f)];
    }
}

// =========== 128x128 FFMA2 tile core (shared by k_gx / k_gemm) =============
// As[16][128], Bs[16][128]; 256 threads; each thread: 8m x 8n, m packed pairs.
struct TileOut { ull acc[4][8]; };

__device__ __forceinline__ void tile_compute(const float* As, const float* Bs,
                                             int ty, int tx, ull acc[4][8]) {
#pragma unroll
    for (int k = 0; k < 16; k++) {
        const float* arow = As + k * 128 + ty * 8;
        const float* brow = Bs + k * 128 + tx * 8;
        ulonglong2 a01 = *(const ulonglong2*)(arow);
        ulonglong2 a23 = *(const ulonglong2*)(arow + 4);
        float4 b0 = *(const float4*)(brow);
        float4 b1 = *(const float4*)(brow + 4);
        ull am[4] = {a01.x, a01.y, a23.x, a23.y};
        ull bb[8] = {dup2(b0.x), dup2(b0.y), dup2(b0.z), dup2(b0.w),
                     dup2(b1.x), dup2(b1.y), dup2(b1.z), dup2(b1.w)};
#pragma unroll
        for (int i = 0; i < 4; i++)
#pragma unroll
            for (int j = 0; j < 8; j++) acc[i][j] = ff2(am[i], bb[j], acc[i][j]);
    }
}

// ---------------- gx = seq @ W_ih^T + b_ih  + fused half-copy ---------------
__global__ __launch_bounds__(256, 2) void k_gx(const float* __restrict__ z,
                                               const float* __restrict__ bih,
                                               const float2* __restrict__ cpA,
                                               const float2* __restrict__ cpB,
                                               float2* __restrict__ cpDst) {
    if (blockIdx.x >= GXB2) {
        if (blockIdx.y != 0) return;
        // second half of passthrough copy
        const long n2 = (long)Bn * Kd * 256 / 2;     // 16,777,216 float2 per tensor
        long i = n2 / 2 + (blockIdx.x - GXB2) * 256L + threadIdx.x;
        const long stride = (long)CPB * 256;
        for (; i < n2; i += stride) {
            cpDst[i]      = cpA[i];
            cpDst[i + n2] = cpB[i];
        }
        return;
    }

    __shared__ float As[16 * 128];
    __shared__ float Bs[16 * 128];
    int tid = threadIdx.x;
    int m0 = blockIdx.x * 128, n0 = blockIdx.y * 128;

    int mA = m0 + (tid & 127);
    int kA0 = tid >> 7;                        // 0..1
    int bq = mA / Tt, tq = mA - bq * Tt;
    const float* aptr = z + (size_t)bq * (Kd * 256) + tq;

    int nB = n0 + (tid & 127);
    int tx = tid & 15, ty = tid >> 4;

    ull acc[4][8];
#pragma unroll
    for (int i = 0; i < 4; i++)
#pragma unroll
        for (int j = 0; j < 8; j++) acc[i][j] = 0ULL;

    for (int kt = 0; kt < Kd; kt += 16) {
#pragma unroll
        for (int i = 0; i < 8; i++) {
            int kl = kA0 + 2 * i;
            As[kl * 128 + (tid & 127)] = aptr[(size_t)(kt + kl) * 256];
            Bs[kl * 128 + (tid & 127)] = g_WihT[(kt + kl) * Gg + nB];
        }
        __syncthreads();
        tile_compute(As, Bs, ty, tx, acc);
        __syncthreads();
    }
    float4 ba = *(const float4*)&bih[n0 + tx * 8];
    float4 bbv = *(const float4*)&bih[n0 + tx * 8 + 4];
    float bias[8] = {ba.x, ba.y, ba.z, ba.w, bbv.x, bbv.y, bbv.z, bbv.w};
#pragma unroll
    for (int i = 0; i < 4; i++) {
        int mlo = m0 + ty * 8 + 2 * i;
        float2 c[8];
#pragma unroll
        for (int j = 0; j < 8; j++) c[j] = unpk2(acc[i][j]);
        float4 vlo0 = {c[0].x + bias[0], c[1].x + bias[1], c[2].x + bias[2], c[3].x + bias[3]};
        float4 vlo1 = {c[4].x + bias[4], c[5].x + bias[5], c[6].x + bias[6], c[7].x + bias[7]};
        float4 vhi0 = {c[0].y + bias[0], c[1].y + bias[1], c[2].y + bias[2], c[3].y + bias[3]};
        float4 vhi1 = {c[4].y + bias[4], c[5].y + bias[5], c[6].y + bias[6], c[7].y + bias[7]};
        *(float4*)&g_gx[(size_t)mlo * Gg + n0 + tx * 8]           = vlo0;
        *(float4*)&g_gx[(size_t)mlo * Gg + n0 + tx * 8 + 4]       = vlo1;
        *(float4*)&g_gx[(size_t)(mlo + 1) * Gg + n0 + tx * 8]     = vhi0;
        *(float4*)&g_gx[(size_t)(mlo + 1) * Gg + n0 + tx * 8 + 4] = vhi1;
    }
}

// ---------------- persistent GRU + fused half-copy --------------------------
__global__ __launch_bounds__(768, 1) void k_gru(const float* __restrict__ h0,
                                                const float* __restrict__ Whh,
                                                const float* __restrict__ bhh,
                                                const float2* __restrict__ cpA,
                                                const float2* __restrict__ cpB,
                                                float2* __restrict__ cpDst) {
    if (blockIdx.x >= (Bn / 4)) {
        // first half of passthrough copy on otherwise-idle SMs
        const long n2 = (long)Bn * Kd * 256 / 2;
        long i = (blockIdx.x - Bn / 4) * 768L + threadIdx.x;
        const long stride = (long)GRUCP * 768;
        const long end = n2 / 2;
        for (; i < end; i += stride) {
            cpDst[i]      = cpA[i];
            cpDst[i + n2] = cpB[i];
        }
        return;
    }

    __shared__ __align__(16) float h_sm[4][128];
    __shared__ float gh_sm[4][Gg];
    __shared__ float bh_sm[Gg];
    int tid = threadIdx.x;
    int b0 = blockIdx.x * 4;
    int g = tid >> 1, half = tid & 1;

    // cache this thread's 64 W_hh weights as 32 packed fp32 pairs
    ull w2[32];
    const ulonglong2* wp = (const ulonglong2*)(Whh + g * KH + half * 64);
#pragma unroll
    for (int i = 0; i < 16; i++) {
        ulonglong2 v = wp[i];
        w2[2 * i] = v.x; w2[2 * i + 1] = v.y;
    }

    if (tid < Gg) bh_sm[tid] = bhh[tid];
    int r2 = tid >> 7, j2 = tid & 127;         // valid for tid<512
    if (tid < 512) h_sm[r2][j2] = h0[(b0 + r2) * KH + j2];
    __syncthreads();

    size_t gxbase = (size_t)(b0 + r2) * Tt * Gg;
    for (int t = 0; t < Tt; t++) {
        float xr = 0.f, xz = 0.f, xn = 0.f;
        if (tid < 512) {
            const float* gp = g_gx + gxbase + (size_t)t * Gg;
            xr = gp[j2]; xz = gp[128 + j2]; xn = gp[256 + j2];
        }
        // phase 1: gh[r][g] = h[r,:] . Whh[g,:]  (8 interleaved FFMA2 chains)
        ull accA[4], accB[4];
#pragma unroll
        for (int r = 0; r < 4; r++) { accA[r] = 0ULL; accB[r] = 0ULL; }
        const ulonglong2* hp0 = (const ulonglong2*)&h_sm[0][half * 64];
        const ulonglong2* hp1 = (const ulonglong2*)&h_sm[1][half * 64];
        const ulonglong2* hp2 = (const ulonglong2*)&h_sm[2][half * 64];
        const ulonglong2* hp3 = (const ulonglong2*)&h_sm[3][half * 64];
#pragma unroll
        for (int i = 0; i < 16; i++) {
            ulonglong2 h0v = hp0[i], h1v = hp1[i], h2v = hp2[i], h3v = hp3[i];
            ull wa = w2[2 * i], wb = w2[2 * i + 1];
            accA[0] = ff2(wa, h0v.x, accA[0]); accB[0] = ff2(wb, h0v.y, accB[0]);
            accA[1] = ff2(wa, h1v.x, accA[1]); accB[1] = ff2(wb, h1v.y, accB[1]);
            accA[2] = ff2(wa, h2v.x, accA[2]); accB[2] = ff2(wb, h2v.y, accB[2]);
            accA[3] = ff2(wa, h3v.x, accA[3]); accB[3] = ff2(wb, h3v.y, accB[3]);
        }
#pragma unroll
        for (int r = 0; r < 4; r++) {
            float2 sa = unpk2(accA[r]), sb = unpk2(accB[r]);
            float acc = (sa.x + sa.y) + (sb.x + sb.y);
            acc += __shfl_xor_sync(0xffffffffu, acc, 1);
            if (half == 0) gh_sm[r][g] = acc;
        }
        __syncthreads();
        // phase 2: gates + state update
        if (tid < 512) {
            float hr = gh_sm[r2][j2]       + bh_sm[j2];
            float hz = gh_sm[r2][128 + j2] + bh_sm[128 + j2];
            float hn = gh_sm[r2][256 + j2] + bh_sm[256 + j2];
            float rr = 1.f / (1.f + __expf(-(xr + hr)));
            float zz = 1.f / (1.f + __expf(-(xz + hz)));
            float nn = tanhf(xn + rr * hn);
            float hp = h_sm[r2][j2];
            h_sm[r2][j2] = (1.f - zz) * nn + zz * hp;
        }
        __syncthreads();
    }
    if (tid < 512) g_ctT[j2 * Bn + (b0 + r2)] = h_sm[r2][j2];
}

// ------------- generic batched GEMM: C[m][n] = sum_k A[k][m]*B[k][n] --------
__global__ __launch_bounds__(256, 2) void k_gemm(const float* __restrict__ A,
                                                 const float* __restrict__ Bm,
                                                 float* __restrict__ C,
                                                 int lda, int ldb, int ldc, int KK,
                                                 long sA, long sB, long sC,
                                                 const float* __restrict__ rowBias, int sBias) {
    __shared__ float As[16 * 128];
    __shared__ float Bs[16 * 128];
    int f = blockIdx.z;
    A += (long)f * sA; Bm += (long)f * sB; C += (long)f * sC;
    int tid = threadIdx.x;
    int m0 = blockIdx.y * 128, n0 = blockIdx.x * 128;
    int mA = m0 + (tid & 127), kA0 = tid >> 7;
    int nB = n0 + (tid & 127);
    int tx = tid & 15, ty = tid >> 4;

    ull acc[4][8];
#pragma unroll
    for (int i = 0; i < 4; i++)
#pragma unroll
        for (int j = 0; j < 8; j++) acc[i][j] = 0ULL;

    for (int kt = 0; kt < KK; kt += 16) {
#pragma unroll
        for (int i = 0; i < 8; i++) {
            int kl = kA0 + 2 * i;
            As[kl * 128 + (tid & 127)] = A[(long)(kt + kl) * lda + mA];
            Bs[kl * 128 + (tid & 127)] = Bm[(long)(kt + kl) * ldb + nB];
        }
        __syncthreads();
        tile_compute(As, Bs, ty, tx, acc);
        __syncthreads();
    }
#pragma unroll
    for (int i = 0; i < 4; i++) {
        int mlo = m0 + ty * 8 + 2 * i;
        float blo = rowBias ? rowBias[(long)f * sBias + mlo] : 0.f;
        float bhi = rowBias ? rowBias[(long)f * sBias + mlo + 1] : 0.f;
        float2 c[8];
#pragma unroll
        for (int j = 0; j < 8; j++) c[j] = unpk2(acc[i][j]);
        float4 vlo0 = {c[0].x + blo, c[1].x + blo, c[2].x + blo, c[3].x + blo};
        float4 vlo1 = {c[4].x + blo, c[5].x + blo, c[6].x + blo, c[7].x + blo};
        float4 vhi0 = {c[0].y + bhi, c[1].y + bhi, c[2].y + bhi, c[3].y + bhi};
        float4 vhi1 = {c[4].y + bhi, c[5].y + bhi, c[6].y + bhi, c[7].y + bhi};
        *(float4*)&C[(long)mlo * ldc + n0 + tx * 8]           = vlo0;
        *(float4*)&C[(long)mlo * ldc + n0 + tx * 8 + 4]       = vlo1;
        *(float4*)&C[(long)(mlo + 1) * ldc + n0 + tx * 8]     = vhi0;
        *(float4*)&C[(long)(mlo + 1) * ldc + n0 + tx * 8 + 4] = vhi1;
    }
}

// ---------------- per-row logsumexp + diagonal of log_softmax --------------
__global__ void k_lse() {
    int row = blockIdx.x;                       // f*512 + b
    const float* p = g_totals + (size_t)row * Bn;
    int tid = threadIdx.x;                      // 128
    __shared__ float sm[128];
    float mx = -1e30f;
    for (int c = tid; c < Bn; c += 128) mx = fmaxf(mx, p[c]);
    sm[tid] = mx; __syncthreads();
    for (int s = 64; s; s >>= 1) { if (tid < s) sm[tid] = fmaxf(sm[tid], sm[tid + s]); __syncthreads(); }
    mx = sm[0]; __syncthreads();
    float sum = 0.f;
    for (int c = tid; c < Bn; c += 128) sum += expf(p[c] - mx);
    sm[tid] = sum; __syncthreads();
    for (int s = 64; s; s >>= 1) { if (tid < s) sm[tid] += sm[tid + s]; __syncthreads(); }
    if (tid == 0) {
        float lse = mx + logf(sm[0]);
        int b = row & 511, f = row >> 9;
        g_diag[row] = p[b] - lse;
        if (f == Ff - 1) g_lse15[b] = lse;
    }
}

// ---------------- accuracy: argmax over b of softmax column ----------------
__global__ void k_acc() {
    int c = blockIdx.x;
    const float* p = g_totals + (size_t)(Ff - 1) * Bn * Bn;
    int tid = threadIdx.x;                      // 128
    float best = -1e30f; int bi = 1 << 30;
    for (int b = tid; b < Bn; b += 128) {
        float v = p[(size_t)b * Bn + c] - g_lse15[b];
        if (v > best) { best = v; bi = b; }
    }
    __shared__ float sv[128]; __shared__ int si[128];
    sv[tid] = best; si[tid] = bi; __syncthreads();
    for (int s = 64; s; s >>= 1) {
        if (tid < s) {
            float v2 = sv[tid + s]; int i2 = si[tid + s];
            if (v2 > sv[tid] || (v2 == sv[tid] && i2 < si[tid])) { sv[tid] = v2; si[tid] = i2; }
        }
        __syncthreads();
    }
    if (tid == 0) g_ok[c] = (si[0] == c) ? 1 : 0;
}

// ---------------- deterministic final reduction -----------------------------
__global__ void k_final(float* __restrict__ out) {
    __shared__ float s[256]; __shared__ int si[256];
    int tid = threadIdx.x;
    float sum = 0.f;
    for (int i = tid; i < Ff * Bn; i += 256) sum += g_diag[i];
    int cnt = 0;
    for (int i = tid; i < Bn; i += 256) cnt += g_ok[i];
    s[tid] = sum; si[tid] = cnt; __syncthreads();
    for (int st = 128; st; st >>= 1) {
        if (tid < st) { s[tid] += s[tid + st]; si[tid] += si[tid + st]; }
        __syncthreads();
    }
    if (tid == 0) {
        out[0] = (float)si[0] / (float)Bn;               // accuracy
        out[1] = -s[0] / (float)(Ff * Bn);               // nce
    }
}

// ---------------- host ----------------
extern "C" void kernel_launch(void* const* d_in, const int* in_sizes, int n_in,
                              void* d_out, int out_size) {
    const float* zqst   = (const float*)d_in[0];
    const float* zex    = (const float*)d_in[1];
    const float* zqx    = (const float*)d_in[2];
    const float* hidden = (const float*)d_in[3];
    const float* Wih = (const float*)d_in[4];
    const float* Whh = (const float*)d_in[5];
    const float* bih = (const float*)d_in[6];
    const float* bhh = (const float*)d_in[7];
    const float* Wkw = (const float*)d_in[8];
    const float* Wkb = (const float*)d_in[9];
    float* out = (float*)d_out;

    float *p_wkT, *p_ctT, *p_predT, *p_encT, *p_totals;
    cudaGetSymbolAddress((void**)&p_wkT,    g_WkT);
    cudaGetSymbolAddress((void**)&p_ctT,    g_ctT);
    cudaGetSymbolAddress((void**)&p_predT,  g_predT);
    cudaGetSymbolAddress((void**)&p_encT,   g_encT);
    cudaGetSymbolAddress((void**)&p_totals, g_totals);

    k_transpose_wih<<<(Gg * Kd + 255) / 256, 256>>>(Wih);
    k_transpose_wk<<<(Ff * Kd * KH + 255) / 256, 256>>>(Wkw);
    k_enc<<<(Ff * Kd * Bn + 255) / 256, 256>>>(zqst);

    // gx GEMM + second half of passthrough copy
    k_gx<<<dim3(GXB2 + CPB, Gg / 128), 256>>>(zqst, bih,
        (const float2*)zex, (const float2*)zqx, (float2*)(out + 2));

    // GRU + first half of passthrough copy on idle SMs
    k_gru<<<Bn / 4 + GRUCP, 768>>>(hidden, Whh, bhh,
        (const float2*)zex, (const float2*)zqx, (float2*)(out + 2));

    // predT[f][k][c] = sum_h WkT[f][h][k] * ctT[h][c] + Wk_b[f][k]
    k_gemm<<<dim3(Bn / 128, Kd / 128, Ff), 256>>>(p_wkT, p_ctT, p_predT,
        Kd, Bn, Bn, KH, (long)KH * Kd, 0L, (long)Kd * Bn, Wkb, Kd);
    // totals[f][b][c] = sum_k encT[f][k][b] * predT[f][k][c]
    k_gemm<<<dim3(Bn / 128, Bn / 128, Ff), 256>>>(p_encT, p_predT, p_totals,
        Bn, Bn, Bn, Kd, (long)Kd * Bn, (long)Kd * Bn, (long)Bn * Bn, nullptr, 0);

    k_lse<<<Ff * Bn, 128>>>();
    k_acc<<<Bn, 128>>>();
    k_final<<<1, 256>>>(out);
}